// round 14
// baseline (speedup 1.0000x reference)
#include <cuda_runtime.h>
#include <cuda_bf16.h>
#include <math.h>
#include <stdint.h>

// Problem constants
constexpr int LL   = 8192;
constexpr int NB   = 2;
constexpr int EE   = 256;
constexpr int HH   = 8;
constexpr int HD   = 32;
constexpr int M    = LL * NB;     // 16384
constexpr int LNE  = M * EE;
constexpr int W4A  = 768 * 256 / 4;
constexpr int W4B  = 256 * 256 / 4;
constexpr int QB4  = LNE / 4 / 256;   // 4096 blocks per qkv tensor
constexpr int WB4  = (W4A + W4B) / 256; // 256 blocks for weights
constexpr float NEG = -1000000000.0f;
constexpr float QSCALE = 0.17677669529663687f;  // 1/sqrt(32)

// Scratch planes
__device__ __align__(16) __nv_bfloat16 g_inh[3 * LNE];
__device__ __align__(16) __nv_bfloat16 g_inl[3 * LNE];
__device__ __align__(16) __nv_bfloat16 g_hi[4 * LNE];
__device__ __align__(16) __nv_bfloat16 g_lo[4 * LNE];
__device__ __align__(16) __nv_bfloat16 g_wh[(W4A + W4B) * 4];
__device__ __align__(16) __nv_bfloat16 g_wl[(W4A + W4B) * 4];

// ---------------------------------------------------------------------------
__device__ __forceinline__ void mma_bf16(float* c,
    uint32_t a0, uint32_t a1, uint32_t a2, uint32_t a3,
    uint32_t b0, uint32_t b1)
{
    asm volatile(
        "mma.sync.aligned.m16n8k16.row.col.f32.bf16.bf16.f32 "
        "{%0,%1,%2,%3}, {%4,%5,%6,%7}, {%8,%9}, {%0,%1,%2,%3};"
        : "+f"(c[0]), "+f"(c[1]), "+f"(c[2]), "+f"(c[3])
        : "r"(a0), "r"(a1), "r"(a2), "r"(a3), "r"(b0), "r"(b1));
}
__device__ __forceinline__ void ldmx4(uint32_t* r, uint32_t addr) {
    asm volatile("ldmatrix.sync.aligned.m8n8.x4.shared.b16 {%0,%1,%2,%3}, [%4];"
        : "=r"(r[0]), "=r"(r[1]), "=r"(r[2]), "=r"(r[3]) : "r"(addr));
}
__device__ __forceinline__ void ldmx4t(uint32_t* r, uint32_t addr) {
    asm volatile("ldmatrix.sync.aligned.m8n8.x4.trans.shared.b16 {%0,%1,%2,%3}, [%4];"
        : "=r"(r[0]), "=r"(r[1]), "=r"(r[2]), "=r"(r[3]) : "r"(addr));
}
__device__ __forceinline__ uint32_t smem_u32(const void* p) {
    uint32_t a;
    asm("{ .reg .u64 t; cvta.to.shared.u64 t, %1; cvt.u32.u64 %0, t; }"
        : "=r"(a) : "l"(p));
    return a;
}
__device__ __forceinline__ void cpasync16(uint32_t s, const void* g) {
    asm volatile("cp.async.cg.shared.global [%0], [%1], 16;" :: "r"(s), "l"(g));
}
__device__ __forceinline__ void cvt_hilo(float x, __nv_bfloat16& h, __nv_bfloat16& l) {
    h = __float2bfloat16_rn(x);
    l = __float2bfloat16_rn(x - __bfloat162float(h));
}
__device__ __forceinline__ void pack2(float a, float b, uint32_t& hi, uint32_t& lo) {
    __nv_bfloat16 ha, la, hb, lb;
    cvt_hilo(a, ha, la);
    cvt_hilo(b, hb, lb);
    __nv_bfloat162 H; H.x = ha; H.y = hb;
    __nv_bfloat162 L; L.x = la; L.y = lb;
    hi = *reinterpret_cast<uint32_t*>(&H);
    lo = *reinterpret_cast<uint32_t*>(&L);
}

// ---------------------------------------------------------------------------
// Single conversion launch: blocks [0, 3*QB4) -> q/k/v planes,
// blocks [3*QB4, 3*QB4+WB4) -> concatenated w_in|w_out planes.
// ---------------------------------------------------------------------------
__global__ __launch_bounds__(256) void cvt_all(
    const float* __restrict__ q, const float* __restrict__ k,
    const float* __restrict__ v,
    const float* __restrict__ w_in, const float* __restrict__ w_out,
    __nv_bfloat16* __restrict__ inh, __nv_bfloat16* __restrict__ inl,
    __nv_bfloat16* __restrict__ wh,  __nv_bfloat16* __restrict__ wl)
{
    const int b = blockIdx.x;
    float4 val;
    uint2 *dh, *dl;
    if (b < 3 * QB4) {
        const int z = b / QB4;
        const int i = (b - z * QB4) * 256 + threadIdx.x;
        const float* x = (z == 0) ? q : (z == 1) ? k : v;
        val = reinterpret_cast<const float4*>(x)[i];
        dh = reinterpret_cast<uint2*>(inh + (size_t)z * LNE) + i;
        dl = reinterpret_cast<uint2*>(inl + (size_t)z * LNE) + i;
    } else {
        const int i = (b - 3 * QB4) * 256 + threadIdx.x;
        val = (i < W4A) ? reinterpret_cast<const float4*>(w_in)[i]
                        : reinterpret_cast<const float4*>(w_out)[i - W4A];
        dh = reinterpret_cast<uint2*>(wh) + i;
        dl = reinterpret_cast<uint2*>(wl) + i;
    }
    __nv_bfloat16 h[4], l[4];
    cvt_hilo(val.x, h[0], l[0]);
    cvt_hilo(val.y, h[1], l[1]);
    cvt_hilo(val.z, h[2], l[2]);
    cvt_hilo(val.w, h[3], l[3]);
    *dh = *reinterpret_cast<uint2*>(h);
    *dl = *reinterpret_cast<uint2*>(l);
}

// ---------------------------------------------------------------------------
// GEMM, BM=64 for finer wave granularity. bf16 hi/lo 3-term, cp.async
// double-buffered, grid.z batched. 8 warps: 2 m-warps x 4 n-warps,
// warp tile 32x16, acc[2][2][4].
// ---------------------------------------------------------------------------
constexpr int BM = 64, BN = 64, BK = 32, LDS_ = BK + 8;  // 40
constexpr int TBUF = BM * LDS_ * 2;            // 5120 per plane per buffer
constexpr int OFF_AH = 0;                      // 2 buffers
constexpr int OFF_AL = 2 * TBUF;               // 10240
constexpr int OFF_BH = 4 * TBUF;               // 20480
constexpr int OFF_BL = 6 * TBUF;               // 30720
constexpr int SMEM_GEMM = 8 * TBUF;            // 40960

template <int MODE>
__global__ __launch_bounds__(256, 3) void gemm_bf16(
    const __nv_bfloat16* __restrict__ Ab,
    const __nv_bfloat16* __restrict__ Alb,
    const __nv_bfloat16* __restrict__ Wb,
    const __nv_bfloat16* __restrict__ Wlb,
    const float* __restrict__ bb,
    float* __restrict__ Cf,
    __nv_bfloat16* __restrict__ Chp,
    __nv_bfloat16* __restrict__ Clp)
{
    extern __shared__ char dsm[];
    const uint32_t sbase = smem_u32(dsm);

    const int z = blockIdx.z;
    const __nv_bfloat16* Ahg = Ab  + (size_t)z * LNE;
    const __nv_bfloat16* Alg = Alb + (size_t)z * LNE;
    const __nv_bfloat16* Whg = Wb  + (size_t)z * EE * EE;
    const __nv_bfloat16* Wlg = Wlb + (size_t)z * EE * EE;
    const float* bias = bb + z * EE;

    const int tid  = threadIdx.x;
    const int lane = tid & 31;
    const int wid  = tid >> 5;
    const int wm   = wid & 1;        // 0..1  (32 rows each)
    const int wn   = wid >> 1;       // 0..3  (16 cols each)
    const int grp  = lane >> 2;
    const int tig  = lane & 3;
    const int m0   = blockIdx.y * BM;
    const int n0   = blockIdx.x * BN;

    float acc[2][2][4];
#pragma unroll
    for (int mt = 0; mt < 2; mt++)
#pragma unroll
        for (int nt = 0; nt < 2; nt++)
#pragma unroll
            for (int i = 0; i < 4; i++) acc[mt][nt][i] = 0.0f;

    const int a_row_l = lane & 15;
    const int a_col_l = (lane >> 4) * 8;
    const int b_row_l = (lane & 7) + ((lane >> 4) << 3);
    const int b_col_l = ((lane >> 3) & 1) * 8;

    // staging: 64 rows x 4 x 16B chunks = 256 tasks, one per thread per plane
    const int s_row = tid >> 2;
    const int s_kc  = (tid & 3) * 8;

    auto stage = [&](int buf, int k0) {
        {
            const size_t g = (size_t)(m0 + s_row) * EE + k0 + s_kc;
            const uint32_t s = sbase + OFF_AH + buf * TBUF + s_row * (LDS_ * 2) + s_kc * 2;
            cpasync16(s, Ahg + g);
            cpasync16(s + (OFF_AL - OFF_AH), Alg + g);
        }
        {
            const size_t g = (size_t)(n0 + s_row) * EE + k0 + s_kc;
            const uint32_t s = sbase + OFF_BH + buf * TBUF + s_row * (LDS_ * 2) + s_kc * 2;
            cpasync16(s, Whg + g);
            cpasync16(s + (OFF_BL - OFF_BH), Wlg + g);
        }
        asm volatile("cp.async.commit_group;");
    };

    stage(0, 0);
    constexpr int NCH = EE / BK;  // 8
#pragma unroll 1
    for (int ch = 0; ch < NCH; ch++) {
        if (ch < NCH - 1) {
            stage((ch + 1) & 1, (ch + 1) * BK);
            asm volatile("cp.async.wait_group 1;");
        } else {
            asm volatile("cp.async.wait_group 0;");
        }
        __syncthreads();

        const int buf = ch & 1;
        const uint32_t sAh = sbase + OFF_AH + buf * TBUF;
        const uint32_t sAl = sbase + OFF_AL + buf * TBUF;
        const uint32_t sBh = sbase + OFF_BH + buf * TBUF;
        const uint32_t sBl = sbase + OFF_BL + buf * TBUF;

#pragma unroll
        for (int ks = 0; ks < 2; ks++) {
            const int kb = ks * 16;
            uint32_t ah[2][4], al[2][4];
#pragma unroll
            for (int mt = 0; mt < 2; mt++) {
                const uint32_t aoff =
                    ((wm * 32 + mt * 16 + a_row_l) * LDS_ + kb + a_col_l) * 2;
                ldmx4(ah[mt], sAh + aoff);
                ldmx4(al[mt], sAl + aoff);
            }
            const uint32_t boff =
                ((wn * 16 + b_row_l) * LDS_ + kb + b_col_l) * 2;
            uint32_t bh[4], bl[4];
            ldmx4(bh, sBh + boff);
            ldmx4(bl, sBl + boff);
#pragma unroll
            for (int nt = 0; nt < 2; nt++) {
                const uint32_t b0h = bh[2 * nt], b1h = bh[2 * nt + 1];
                const uint32_t b0l = bl[2 * nt], b1l = bl[2 * nt + 1];
#pragma unroll
                for (int mt = 0; mt < 2; mt++) {
                    mma_bf16(acc[mt][nt], ah[mt][0], ah[mt][1], ah[mt][2], ah[mt][3], b0h, b1h);
                    mma_bf16(acc[mt][nt], ah[mt][0], ah[mt][1], ah[mt][2], ah[mt][3], b0l, b1l);
                    mma_bf16(acc[mt][nt], al[mt][0], al[mt][1], al[mt][2], al[mt][3], b0h, b1h);
                }
            }
        }
        __syncthreads();
    }

    if (MODE == 0) {
        float* C = Cf;
#pragma unroll
        for (int mt = 0; mt < 2; mt++) {
            const int r0 = m0 + wm * 32 + mt * 16 + grp;
#pragma unroll
            for (int nt = 0; nt < 2; nt++) {
                const int c = n0 + wn * 16 + nt * 8 + 2 * tig;
                const float b0v = bias[c], b1v = bias[c + 1];
                float2 o0 = make_float2(acc[mt][nt][0] + b0v, acc[mt][nt][1] + b1v);
                float2 o1 = make_float2(acc[mt][nt][2] + b0v, acc[mt][nt][3] + b1v);
                *reinterpret_cast<float2*>(&C[(size_t)r0 * EE + c]) = o0;
                *reinterpret_cast<float2*>(&C[(size_t)(r0 + 8) * EE + c]) = o1;
            }
        }
    } else {
        const float sc = (z == 0) ? QSCALE : 1.0f;
        __nv_bfloat16* Ch = Chp + (size_t)z * LNE;
        __nv_bfloat16* Cl = Clp + (size_t)z * LNE;
#pragma unroll
        for (int mt = 0; mt < 2; mt++) {
            const int r0 = m0 + wm * 32 + mt * 16 + grp;
#pragma unroll
            for (int nt = 0; nt < 2; nt++) {
                const int c = n0 + wn * 16 + nt * 8 + 2 * tig;
                const float b0v = bias[c], b1v = bias[c + 1];
                uint32_t hi0, lo0, hi1, lo1;
                pack2((acc[mt][nt][0] + b0v) * sc, (acc[mt][nt][1] + b1v) * sc, hi0, lo0);
                pack2((acc[mt][nt][2] + b0v) * sc, (acc[mt][nt][3] + b1v) * sc, hi1, lo1);
                *reinterpret_cast<uint32_t*>(&Ch[(size_t)r0 * EE + c]) = hi0;
                *reinterpret_cast<uint32_t*>(&Cl[(size_t)r0 * EE + c]) = lo0;
                *reinterpret_cast<uint32_t*>(&Ch[(size_t)(r0 + 8) * EE + c]) = hi1;
                *reinterpret_cast<uint32_t*>(&Cl[(size_t)(r0 + 8) * EE + c]) = lo1;
            }
        }
    }
}

// ---------------------------------------------------------------------------
// Banded MMA sliding-window attention (unchanged from R13: 26.0 us measured).
// ---------------------------------------------------------------------------
constexpr int TLQ = 64, KR = 96;
constexpr int KSTR = 40;
constexpr int PSTR = 56;
constexpr int AOFF_QH = 0;
constexpr int AOFF_QL = AOFF_QH + TLQ * KSTR * 2;
constexpr int AOFF_KH = AOFF_QL + TLQ * KSTR * 2;
constexpr int AOFF_KL = AOFF_KH + KR * KSTR * 2;
constexpr int AOFF_VH = AOFF_KL + KR * KSTR * 2;
constexpr int AOFF_VL = AOFF_VH + KR * KSTR * 2;
constexpr int AOFF_PH = AOFF_VL + KR * KSTR * 2;
constexpr int AOFF_PL = AOFF_PH + TLQ * PSTR * 2;
constexpr int AOFF_DEN = AOFF_PL + TLQ * PSTR * 2;
constexpr int SMEM_ATTN = AOFF_DEN + TLQ * 2 * 4;   // 55808

__global__ __launch_bounds__(256, 3) void attn_mma(
    const __nv_bfloat16* __restrict__ qh, const __nv_bfloat16* __restrict__ ql,
    const __nv_bfloat16* __restrict__ kh, const __nv_bfloat16* __restrict__ kl,
    const __nv_bfloat16* __restrict__ vh, const __nv_bfloat16* __restrict__ vl,
    __nv_bfloat16* __restrict__ oh, __nv_bfloat16* __restrict__ ol)
{
    extern __shared__ char dsm[];
    const uint32_t sb = smem_u32(dsm);

    const int nhid = blockIdx.y;
    const int n    = nhid / HH;
    const int h    = nhid % HH;
    const int l0   = blockIdx.x * TLQ;
    const int tid  = threadIdx.x;
    const int lane = tid & 31;
    const int wid  = tid >> 5;
    const int mt   = wid & 3;
    const int nhf  = wid >> 2;
    const int grp  = lane >> 2;
    const int tig  = lane & 3;

    {
        const int row = tid >> 2, ch = tid & 3;
        const size_t src = ((size_t)(l0 + row) * NB + n) * EE + h * HD + ch * 8;
        const uint32_t dst = sb + AOFF_QH + row * (KSTR * 2) + ch * 16;
        cpasync16(dst, qh + src);
        cpasync16(dst + (AOFF_QL - AOFF_QH), ql + src);
    }
#pragma unroll
    for (int i = 0; i < 2; i++) {
        const int idx = tid + i * 256;
        if (idx < KR * 4) {
            const int row = idx >> 2, ch = idx & 3;
            const int gl = l0 - 32 + row;
            const uint32_t dk = sb + AOFF_KH + row * (KSTR * 2) + ch * 16;
            const uint32_t dv = sb + AOFF_VH + row * (KSTR * 2) + ch * 16;
            if (gl >= 0) {
                const size_t src = ((size_t)gl * NB + n) * EE + h * HD + ch * 8;
                cpasync16(dk, kh + src);
                cpasync16(dk + (AOFF_KL - AOFF_KH), kl + src);
                cpasync16(dv, vh + src);
                cpasync16(dv + (AOFF_VL - AOFF_VH), vl + src);
            } else {
                const uint4 z4 = make_uint4(0, 0, 0, 0);
                const int bo = row * (KSTR * 2) + ch * 16;
                *reinterpret_cast<uint4*>(dsm + AOFF_KH + bo) = z4;
                *reinterpret_cast<uint4*>(dsm + AOFF_KL + bo) = z4;
                *reinterpret_cast<uint4*>(dsm + AOFF_VH + bo) = z4;
                *reinterpret_cast<uint4*>(dsm + AOFF_VL + bo) = z4;
            }
        }
    }
    asm volatile("cp.async.commit_group;");
    asm volatile("cp.async.wait_group 0;");
    __syncthreads();

    const int a_row_l = lane & 15;
    const int a_col_l = (lane >> 4) * 8;
    const int b_row_l = (lane & 7) + ((lane >> 4) << 3);
    const int b_col_l = ((lane >> 3) & 1) * 8;

    float scacc[3][4];
#pragma unroll
    for (int t = 0; t < 3; t++)
#pragma unroll
        for (int i = 0; i < 4; i++) scacc[t][i] = 0.0f;

#pragma unroll
    for (int ks = 0; ks < 2; ks++) {
        const int kb = ks * 16;
        uint32_t qa[4], qb[4];
        const uint32_t aoff = (mt * 16 + a_row_l) * (KSTR * 2) + (kb + a_col_l) * 2;
        ldmx4(qa, sb + AOFF_QH + aoff);
        ldmx4(qb, sb + AOFF_QL + aoff);
        const uint32_t b0off = (mt * 16 + nhf * 16 + b_row_l) * (KSTR * 2) + (kb + b_col_l) * 2;
        const uint32_t b1off = (mt * 16 + 32 + b_row_l) * (KSTR * 2) + (kb + b_col_l) * 2;
        uint32_t k0h[4], k0l[4], k1h[4], k1l[4];
        ldmx4(k0h, sb + AOFF_KH + b0off);
        ldmx4(k0l, sb + AOFF_KL + b0off);
        ldmx4(k1h, sb + AOFF_KH + b1off);
        ldmx4(k1l, sb + AOFF_KL + b1off);
#pragma unroll
        for (int j = 0; j < 2; j++) {
            mma_bf16(scacc[j], qa[0], qa[1], qa[2], qa[3], k0h[2 * j], k0h[2 * j + 1]);
            mma_bf16(scacc[j], qa[0], qa[1], qa[2], qa[3], k0l[2 * j], k0l[2 * j + 1]);
            mma_bf16(scacc[j], qb[0], qb[1], qb[2], qb[3], k0h[2 * j], k0h[2 * j + 1]);
        }
        mma_bf16(scacc[2], qa[0], qa[1], qa[2], qa[3], k1h[2 * nhf], k1h[2 * nhf + 1]);
        mma_bf16(scacc[2], qa[0], qa[1], qa[2], qa[3], k1l[2 * nhf], k1l[2 * nhf + 1]);
        mma_bf16(scacc[2], qb[0], qb[1], qb[2], qb[3], k1h[2 * nhf], k1h[2 * nhf + 1]);
    }

    const int rr0 = grp;
    const int rr1 = grp + 8;
    const int prow0 = mt * 16 + grp;
    const int prow1 = prow0 + 8;
    float sA = 0.0f, sB = 0.0f;
#pragma unroll
    for (int t = 0; t < 3; t++) {
        const int cc0 = ((t < 2) ? (nhf * 16 + t * 8) : (32 + nhf * 8)) + 2 * tig;
        const int cc1 = cc0 + 1;
        const int gbase = l0 + mt * 16;
        const float m00 = (cc0 >= rr0 && cc0 <= rr0 + 32 && gbase + cc0 >= 32) ? 0.0f : NEG;
        const float m01 = (cc1 >= rr0 && cc1 <= rr0 + 32 && gbase + cc1 >= 32) ? 0.0f : NEG;
        const float m10 = (cc0 >= rr1 && cc0 <= rr1 + 32 && gbase + cc0 >= 32) ? 0.0f : NEG;
        const float m11 = (cc1 >= rr1 && cc1 <= rr1 + 32 && gbase + cc1 >= 32) ? 0.0f : NEG;
        const float e00 = __expf(scacc[t][0] + m00);
        const float e01 = __expf(scacc[t][1] + m01);
        const float e10 = __expf(scacc[t][2] + m10);
        const float e11 = __expf(scacc[t][3] + m11);
        sA += e00 + e01;
        sB += e10 + e11;
        uint32_t hi0, lo0, hi1, lo1;
        pack2(e00, e01, hi0, lo0);
        pack2(e10, e11, hi1, lo1);
        const int bo0 = (prow0 * PSTR + cc0) * 2;
        const int bo1 = (prow1 * PSTR + cc0) * 2;
        *reinterpret_cast<uint32_t*>(dsm + AOFF_PH + bo0) = hi0;
        *reinterpret_cast<uint32_t*>(dsm + AOFF_PL + bo0) = lo0;
        *reinterpret_cast<uint32_t*>(dsm + AOFF_PH + bo1) = hi1;
        *reinterpret_cast<uint32_t*>(dsm + AOFF_PL + bo1) = lo1;
    }
    sA += __shfl_xor_sync(0xFFFFFFFFu, sA, 1);
    sA += __shfl_xor_sync(0xFFFFFFFFu, sA, 2);
    sB += __shfl_xor_sync(0xFFFFFFFFu, sB, 1);
    sB += __shfl_xor_sync(0xFFFFFFFFu, sB, 2);
    if (tig == 0) {
        *reinterpret_cast<float*>(dsm + AOFF_DEN + (prow0 * 2 + nhf) * 4) = sA;
        *reinterpret_cast<float*>(dsm + AOFF_DEN + (prow1 * 2 + nhf) * 4) = sB;
    }
    __syncthreads();

    float oacc[2][4];
#pragma unroll
    for (int j = 0; j < 2; j++)
#pragma unroll
        for (int i = 0; i < 4; i++) oacc[j][i] = 0.0f;

#pragma unroll
    for (int ks = 0; ks < 3; ks++) {
        const int kb = ks * 16;
        uint32_t pa[4], pb[4];
        const uint32_t aoff = (mt * 16 + a_row_l) * (PSTR * 2) + (kb + a_col_l) * 2;
        ldmx4(pa, sb + AOFF_PH + aoff);
        ldmx4(pb, sb + AOFF_PL + aoff);
        const uint32_t voff =
            (mt * 16 + kb + a_row_l) * (KSTR * 2) + nhf * 32 + (lane >> 4) * 16;
        uint32_t vth[4], vtl[4];
        ldmx4t(vth, sb + AOFF_VH + voff);
        ldmx4t(vtl, sb + AOFF_VL + voff);
#pragma unroll
        for (int j = 0; j < 2; j++) {
            mma_bf16(oacc[j], pa[0], pa[1], pa[2], pa[3], vth[2 * j], vth[2 * j + 1]);
            mma_bf16(oacc[j], pa[0], pa[1], pa[2], pa[3], vtl[2 * j], vtl[2 * j + 1]);
            mma_bf16(oacc[j], pb[0], pb[1], pb[2], pb[3], vth[2 * j], vth[2 * j + 1]);
        }
    }

    const float dA = *reinterpret_cast<float*>(dsm + AOFF_DEN + prow0 * 8) +
                     *reinterpret_cast<float*>(dsm + AOFF_DEN + prow0 * 8 + 4);
    const float dB = *reinterpret_cast<float*>(dsm + AOFF_DEN + prow1 * 8) +
                     *reinterpret_cast<float*>(dsm + AOFF_DEN + prow1 * 8 + 4);
    const float invA = 1.0f / dA;
    const float invB = 1.0f / dB;
    const size_t base0 = ((size_t)(l0 + prow0) * NB + n) * EE + h * HD;
    const size_t base1 = ((size_t)(l0 + prow1) * NB + n) * EE + h * HD;
#pragma unroll
    for (int j = 0; j < 2; j++) {
        const int d0 = nhf * 16 + j * 8 + 2 * tig;
        uint32_t hi0, lo0, hi1, lo1;
        pack2(oacc[j][0] * invA, oacc[j][1] * invA, hi0, lo0);
        pack2(oacc[j][2] * invB, oacc[j][3] * invB, hi1, lo1);
        *reinterpret_cast<uint32_t*>(oh + base0 + d0) = hi0;
        *reinterpret_cast<uint32_t*>(ol + base0 + d0) = lo0;
        *reinterpret_cast<uint32_t*>(oh + base1 + d0) = hi1;
        *reinterpret_cast<uint32_t*>(ol + base1 + d0) = lo1;
    }
}

// ---------------------------------------------------------------------------
extern "C" void kernel_launch(void* const* d_in, const int* in_sizes, int n_in,
                              void* d_out, int out_size)
{
    const float* query = (const float*)d_in[0];
    const float* key   = (const float*)d_in[1];
    const float* value = (const float*)d_in[2];
    const float* w_in  = (const float*)d_in[3];
    const float* b_in  = (const float*)d_in[4];
    const float* w_out = (const float*)d_in[5];
    const float* b_out = (const float*)d_in[6];
    float* out = (float*)d_out;

    __nv_bfloat16 *inh = nullptr, *inl = nullptr, *hi = nullptr, *lo = nullptr;
    __nv_bfloat16 *wh = nullptr, *wl = nullptr;
    cudaGetSymbolAddress((void**)&inh, g_inh);
    cudaGetSymbolAddress((void**)&inl, g_inl);
    cudaGetSymbolAddress((void**)&hi,  g_hi);
    cudaGetSymbolAddress((void**)&lo,  g_lo);
    cudaGetSymbolAddress((void**)&wh,  g_wh);
    cudaGetSymbolAddress((void**)&wl,  g_wl);

    __nv_bfloat16 *wih = wh, *wil = wl;
    __nv_bfloat16 *woh = wh + 768 * 256, *wol = wl + 768 * 256;
    __nv_bfloat16 *ohp = hi + 3 * (size_t)LNE, *olp = lo + 3 * (size_t)LNE;

    cudaFuncSetAttribute(gemm_bf16<0>,
        cudaFuncAttributeMaxDynamicSharedMemorySize, SMEM_GEMM);
    cudaFuncSetAttribute(gemm_bf16<1>,
        cudaFuncAttributeMaxDynamicSharedMemorySize, SMEM_GEMM);
    cudaFuncSetAttribute(attn_mma,
        cudaFuncAttributeMaxDynamicSharedMemorySize, SMEM_ATTN);

    // All conversions in one launch
    cvt_all<<<3 * QB4 + WB4, 256>>>(query, key, value, w_in, w_out,
                                    inh, inl, wh, wl);

    // Batched q/k/v projections -> hi/lo planes (q scaled). grid 3072 CTAs.
    gemm_bf16<1><<<dim3(EE / BN, M / BM, 3), 256, SMEM_GEMM>>>(
        inh, inl, wih, wil, b_in, nullptr, hi, lo);

    attn_mma<<<dim3(LL / TLQ, NB * HH), 256, SMEM_ATTN>>>(
        hi, lo, hi + LNE, lo + LNE, hi + 2 * (size_t)LNE, lo + 2 * (size_t)LNE,
        ohp, olp);

    // Out-projection. grid 1024 CTAs.
    gemm_bf16<0><<<dim3(EE / BN, M / BM, 1), 256, SMEM_GEMM>>>(
        ohp, olp, woh, wol, b_out, out, nullptr, nullptr);
}

// round 15
// speedup vs baseline: 1.3448x; 1.3448x over previous
#include <cuda_runtime.h>
#include <cuda_fp16.h>
#include <math.h>
#include <stdint.h>

// Problem constants
constexpr int LL   = 8192;
constexpr int NB   = 2;
constexpr int EE   = 256;
constexpr int HH   = 8;
constexpr int HD   = 32;
constexpr int M    = LL * NB;     // 16384
constexpr int LNE  = M * EE;
constexpr int W4A  = 768 * 256 / 4;
constexpr int W4B  = 256 * 256 / 4;
constexpr int QB4  = LNE / 4 / 256;     // 4096 blocks per qkv tensor
constexpr int WB4  = (W4A + W4B) / 256; // 256 blocks for weights
constexpr float NEG = -1000000000.0f;
constexpr float QSCALE = 0.17677669529663687f;  // 1/sqrt(32)

// Scratch planes (fp16)
__device__ __align__(16) __half g_inh[3 * LNE];   // raw q,k,v hi
__device__ __align__(16) __half g_inl[3 * LNE];   // raw q,k,v lo
__device__ __align__(16) __half g_hi[4 * LNE];    // proj q,k,v + attn-out hi
__device__ __align__(16) __half g_lo[4 * LNE];    // lo (k slot unused)
__device__ __align__(16) __half g_wh[(W4A + W4B) * 4];  // weights single fp16

// ---------------------------------------------------------------------------
__device__ __forceinline__ void mma_fp16(float* c,
    uint32_t a0, uint32_t a1, uint32_t a2, uint32_t a3,
    uint32_t b0, uint32_t b1)
{
    asm volatile(
        "mma.sync.aligned.m16n8k16.row.col.f32.f16.f16.f32 "
        "{%0,%1,%2,%3}, {%4,%5,%6,%7}, {%8,%9}, {%0,%1,%2,%3};"
        : "+f"(c[0]), "+f"(c[1]), "+f"(c[2]), "+f"(c[3])
        : "r"(a0), "r"(a1), "r"(a2), "r"(a3), "r"(b0), "r"(b1));
}
__device__ __forceinline__ void ldmx4(uint32_t* r, uint32_t addr) {
    asm volatile("ldmatrix.sync.aligned.m8n8.x4.shared.b16 {%0,%1,%2,%3}, [%4];"
        : "=r"(r[0]), "=r"(r[1]), "=r"(r[2]), "=r"(r[3]) : "r"(addr));
}
__device__ __forceinline__ void ldmx4t(uint32_t* r, uint32_t addr) {
    asm volatile("ldmatrix.sync.aligned.m8n8.x4.trans.shared.b16 {%0,%1,%2,%3}, [%4];"
        : "=r"(r[0]), "=r"(r[1]), "=r"(r[2]), "=r"(r[3]) : "r"(addr));
}
__device__ __forceinline__ uint32_t smem_u32(const void* p) {
    uint32_t a;
    asm("{ .reg .u64 t; cvta.to.shared.u64 t, %1; cvt.u32.u64 %0, t; }"
        : "=r"(a) : "l"(p));
    return a;
}
__device__ __forceinline__ void cpasync16(uint32_t s, const void* g) {
    asm volatile("cp.async.cg.shared.global [%0], [%1], 16;" :: "r"(s), "l"(g));
}
__device__ __forceinline__ void cvt_hilo(float x, __half& h, __half& l) {
    h = __float2half_rn(x);
    l = __float2half_rn(x - __half2float(h));
}
// pack two floats into fp16 hi-pair and lo-pair words
__device__ __forceinline__ void pack2(float a, float b, uint32_t& hi, uint32_t& lo) {
    __half ha, la, hb, lb;
    cvt_hilo(a, ha, la);
    cvt_hilo(b, hb, lb);
    __half2 H; H.x = ha; H.y = hb;
    __half2 L; L.x = la; L.y = lb;
    hi = *reinterpret_cast<uint32_t*>(&H);
    lo = *reinterpret_cast<uint32_t*>(&L);
}
// pack two floats into one fp16 pair (single rounding)
__device__ __forceinline__ uint32_t pack1(float a, float b) {
    __half2 H; H.x = __float2half_rn(a); H.y = __float2half_rn(b);
    return *reinterpret_cast<uint32_t*>(&H);
}

// ---------------------------------------------------------------------------
// Single conversion launch: blocks [0, 3*QB4) -> q/k/v hi/lo planes,
// blocks [3*QB4, 3*QB4+WB4) -> concatenated w_in|w_out single plane.
// ---------------------------------------------------------------------------
__global__ __launch_bounds__(256) void cvt_all(
    const float* __restrict__ q, const float* __restrict__ k,
    const float* __restrict__ v,
    const float* __restrict__ w_in, const float* __restrict__ w_out,
    __half* __restrict__ inh, __half* __restrict__ inl,
    __half* __restrict__ wh)
{
    const int b = blockIdx.x;
    if (b < 3 * QB4) {
        const int z = b / QB4;
        const int i = (b - z * QB4) * 256 + threadIdx.x;
        const float* x = (z == 0) ? q : (z == 1) ? k : v;
        float4 val = reinterpret_cast<const float4*>(x)[i];
        __half h[4], l[4];
        cvt_hilo(val.x, h[0], l[0]);
        cvt_hilo(val.y, h[1], l[1]);
        cvt_hilo(val.z, h[2], l[2]);
        cvt_hilo(val.w, h[3], l[3]);
        reinterpret_cast<uint2*>(inh + (size_t)z * LNE)[i] = *reinterpret_cast<uint2*>(h);
        reinterpret_cast<uint2*>(inl + (size_t)z * LNE)[i] = *reinterpret_cast<uint2*>(l);
    } else {
        const int i = (b - 3 * QB4) * 256 + threadIdx.x;
        float4 val = (i < W4A) ? reinterpret_cast<const float4*>(w_in)[i]
                               : reinterpret_cast<const float4*>(w_out)[i - W4A];
        __half h[4];
        h[0] = __float2half_rn(val.x);
        h[1] = __float2half_rn(val.y);
        h[2] = __float2half_rn(val.z);
        h[3] = __float2half_rn(val.w);
        reinterpret_cast<uint2*>(wh)[i] = *reinterpret_cast<uint2*>(h);
    }
}

// ---------------------------------------------------------------------------
// GEMM fp16 2-term: C = (Ah+Al) * W^T + bias, A split hi/lo, W single fp16.
// BM=128, BN=64, BK=32, cp.async double-buffered, grid.z batched.
// MODE 0: fp32 C out. MODE 1: fp16 hi/lo planes out (k lo skipped), q scaled.
// ---------------------------------------------------------------------------
constexpr int BM = 128, BN = 64, BK = 32, LDS_ = BK + 8;  // 40
constexpr int ABUF = BM * LDS_ * 2;            // 10240
constexpr int BBUF = BN * LDS_ * 2;            // 5120
constexpr int OFF_AH = 0;                      // 2 buffers
constexpr int OFF_AL = 2 * ABUF;               // 20480
constexpr int OFF_BH = 4 * ABUF;               // 40960
constexpr int SMEM_GEMM = OFF_BH + 2 * BBUF;   // 51200

template <int MODE>
__global__ __launch_bounds__(256, 3) void gemm_fp16(
    const __half* __restrict__ Ab,
    const __half* __restrict__ Alb,
    const __half* __restrict__ Wb,
    const float* __restrict__ bb,
    float* __restrict__ Cf,
    __half* __restrict__ Chp,
    __half* __restrict__ Clp)
{
    extern __shared__ char dsm[];
    const uint32_t sbase = smem_u32(dsm);

    const int z = blockIdx.z;
    const __half* Ahg = Ab  + (size_t)z * LNE;
    const __half* Alg = Alb + (size_t)z * LNE;
    const __half* Whg = Wb  + (size_t)z * EE * EE;
    const float* bias = bb + z * EE;

    const int tid  = threadIdx.x;
    const int lane = tid & 31;
    const int wid  = tid >> 5;
    const int wm   = wid & 3;
    const int wn   = wid >> 2;
    const int grp  = lane >> 2;
    const int tig  = lane & 3;
    const int m0   = blockIdx.y * BM;
    const int n0   = blockIdx.x * BN;

    float acc[2][4][4];
#pragma unroll
    for (int mt = 0; mt < 2; mt++)
#pragma unroll
        for (int nt = 0; nt < 4; nt++)
#pragma unroll
            for (int i = 0; i < 4; i++) acc[mt][nt][i] = 0.0f;

    const int a_row_l = lane & 15;
    const int a_col_l = (lane >> 4) * 8;
    const int b_row_l = (lane & 7) + ((lane >> 4) << 3);
    const int b_col_l = ((lane >> 3) & 1) * 8;

    const int sa_row = tid >> 2;
    const int sa_kc  = (tid & 3) * 8;

    auto stage = [&](int buf, int k0) {
#pragma unroll
        for (int p = 0; p < 2; p++) {
            const int row = sa_row + p * 64;
            const size_t g = (size_t)(m0 + row) * EE + k0 + sa_kc;
            const uint32_t s = sbase + OFF_AH + buf * ABUF + row * (LDS_ * 2) + sa_kc * 2;
            cpasync16(s, Ahg + g);
            cpasync16(s + (OFF_AL - OFF_AH), Alg + g);
        }
        {
            const size_t g = (size_t)(n0 + sa_row) * EE + k0 + sa_kc;
            const uint32_t s = sbase + OFF_BH + buf * BBUF + sa_row * (LDS_ * 2) + sa_kc * 2;
            cpasync16(s, Whg + g);
        }
        asm volatile("cp.async.commit_group;");
    };

    stage(0, 0);
    constexpr int NCH = EE / BK;
#pragma unroll 1
    for (int ch = 0; ch < NCH; ch++) {
        if (ch < NCH - 1) {
            stage((ch + 1) & 1, (ch + 1) * BK);
            asm volatile("cp.async.wait_group 1;");
        } else {
            asm volatile("cp.async.wait_group 0;");
        }
        __syncthreads();

        const int buf = ch & 1;
        const uint32_t sAh = sbase + OFF_AH + buf * ABUF;
        const uint32_t sAl = sbase + OFF_AL + buf * ABUF;
        const uint32_t sBh = sbase + OFF_BH + buf * BBUF;

#pragma unroll
        for (int ks = 0; ks < 2; ks++) {
            const int kb = ks * 16;
            uint32_t ah[2][4], al[2][4];
#pragma unroll
            for (int mt = 0; mt < 2; mt++) {
                const uint32_t aoff =
                    ((wm * 32 + mt * 16 + a_row_l) * LDS_ + kb + a_col_l) * 2;
                ldmx4(ah[mt], sAh + aoff);
                ldmx4(al[mt], sAl + aoff);
            }
#pragma unroll
            for (int ntp = 0; ntp < 2; ntp++) {
                const uint32_t boff =
                    ((wn * 32 + ntp * 16 + b_row_l) * LDS_ + kb + b_col_l) * 2;
                uint32_t bh[4];
                ldmx4(bh, sBh + boff);
#pragma unroll
                for (int j = 0; j < 2; j++) {
                    const int nt = ntp * 2 + j;
                    const uint32_t b0h = bh[2 * j], b1h = bh[2 * j + 1];
#pragma unroll
                    for (int mt = 0; mt < 2; mt++) {
                        mma_fp16(acc[mt][nt], ah[mt][0], ah[mt][1], ah[mt][2], ah[mt][3], b0h, b1h);
                        mma_fp16(acc[mt][nt], al[mt][0], al[mt][1], al[mt][2], al[mt][3], b0h, b1h);
                    }
                }
            }
        }
        __syncthreads();
    }

    if (MODE == 0) {
        float* C = Cf;
#pragma unroll
        for (int mt = 0; mt < 2; mt++) {
            const int r0 = m0 + wm * 32 + mt * 16 + grp;
#pragma unroll
            for (int nt = 0; nt < 4; nt++) {
                const int c = n0 + wn * 32 + nt * 8 + 2 * tig;
                const float b0v = bias[c], b1v = bias[c + 1];
                float2 o0 = make_float2(acc[mt][nt][0] + b0v, acc[mt][nt][1] + b1v);
                float2 o1 = make_float2(acc[mt][nt][2] + b0v, acc[mt][nt][3] + b1v);
                *reinterpret_cast<float2*>(&C[(size_t)r0 * EE + c]) = o0;
                *reinterpret_cast<float2*>(&C[(size_t)(r0 + 8) * EE + c]) = o1;
            }
        }
    } else {
        const float sc = (z == 0) ? QSCALE : 1.0f;
        __half* Ch = Chp + (size_t)z * LNE;
        __half* Cl = Clp + (size_t)z * LNE;
        const bool wlo = (z != 1);   // k consumed as single fp16 (B operand)
#pragma unroll
        for (int mt = 0; mt < 2; mt++) {
            const int r0 = m0 + wm * 32 + mt * 16 + grp;
#pragma unroll
            for (int nt = 0; nt < 4; nt++) {
                const int c = n0 + wn * 32 + nt * 8 + 2 * tig;
                const float b0v = bias[c], b1v = bias[c + 1];
                uint32_t hi0, lo0, hi1, lo1;
                pack2((acc[mt][nt][0] + b0v) * sc, (acc[mt][nt][1] + b1v) * sc, hi0, lo0);
                pack2((acc[mt][nt][2] + b0v) * sc, (acc[mt][nt][3] + b1v) * sc, hi1, lo1);
                *reinterpret_cast<uint32_t*>(&Ch[(size_t)r0 * EE + c]) = hi0;
                *reinterpret_cast<uint32_t*>(&Ch[(size_t)(r0 + 8) * EE + c]) = hi1;
                if (wlo) {
                    *reinterpret_cast<uint32_t*>(&Cl[(size_t)r0 * EE + c]) = lo0;
                    *reinterpret_cast<uint32_t*>(&Cl[(size_t)(r0 + 8) * EE + c]) = lo1;
                }
            }
        }
    }
}

// ---------------------------------------------------------------------------
// Banded MMA sliding-window attention, fp16 2-term.
// Q hi/lo x K single (scores); P single x V hi/lo (output).
// ---------------------------------------------------------------------------
constexpr int TLQ = 64, KR = 96;
constexpr int KSTR = 40;
constexpr int PSTR = 56;
constexpr int AOFF_QH = 0;
constexpr int AOFF_QL = AOFF_QH + TLQ * KSTR * 2;   // 5120
constexpr int AOFF_KH = AOFF_QL + TLQ * KSTR * 2;   // 10240
constexpr int AOFF_VH = AOFF_KH + KR * KSTR * 2;    // 17920
constexpr int AOFF_VL = AOFF_VH + KR * KSTR * 2;    // 25600
constexpr int AOFF_PH = AOFF_VL + KR * KSTR * 2;    // 33280
constexpr int AOFF_DEN = AOFF_PH + TLQ * PSTR * 2;  // 40448
constexpr int SMEM_ATTN = AOFF_DEN + TLQ * 2 * 4;   // 40960

__global__ __launch_bounds__(256, 3) void attn_mma(
    const __half* __restrict__ qh, const __half* __restrict__ ql,
    const __half* __restrict__ kh,
    const __half* __restrict__ vh, const __half* __restrict__ vl,
    __half* __restrict__ oh, __half* __restrict__ ol)
{
    extern __shared__ char dsm[];
    const uint32_t sb = smem_u32(dsm);

    const int nhid = blockIdx.y;
    const int n    = nhid / HH;
    const int h    = nhid % HH;
    const int l0   = blockIdx.x * TLQ;
    const int tid  = threadIdx.x;
    const int lane = tid & 31;
    const int wid  = tid >> 5;
    const int mt   = wid & 3;
    const int nhf  = wid >> 2;
    const int grp  = lane >> 2;
    const int tig  = lane & 3;

    // --- stage Q (hi/lo)
    {
        const int row = tid >> 2, ch = tid & 3;
        const size_t src = ((size_t)(l0 + row) * NB + n) * EE + h * HD + ch * 8;
        const uint32_t dst = sb + AOFF_QH + row * (KSTR * 2) + ch * 16;
        cpasync16(dst, qh + src);
        cpasync16(dst + (AOFF_QL - AOFF_QH), ql + src);
    }
    // --- stage K (single), V (hi/lo)
#pragma unroll
    for (int i = 0; i < 2; i++) {
        const int idx = tid + i * 256;
        if (idx < KR * 4) {
            const int row = idx >> 2, ch = idx & 3;
            const int gl = l0 - 32 + row;
            const uint32_t dk = sb + AOFF_KH + row * (KSTR * 2) + ch * 16;
            const uint32_t dv = sb + AOFF_VH + row * (KSTR * 2) + ch * 16;
            if (gl >= 0) {
                const size_t src = ((size_t)gl * NB + n) * EE + h * HD + ch * 8;
                cpasync16(dk, kh + src);
                cpasync16(dv, vh + src);
                cpasync16(dv + (AOFF_VL - AOFF_VH), vl + src);
            } else {
                const uint4 z4 = make_uint4(0, 0, 0, 0);
                const int bo = row * (KSTR * 2) + ch * 16;
                *reinterpret_cast<uint4*>(dsm + AOFF_KH + bo) = z4;
                *reinterpret_cast<uint4*>(dsm + AOFF_VH + bo) = z4;
                *reinterpret_cast<uint4*>(dsm + AOFF_VL + bo) = z4;
            }
        }
    }
    asm volatile("cp.async.commit_group;");
    asm volatile("cp.async.wait_group 0;");
    __syncthreads();

    const int a_row_l = lane & 15;
    const int a_col_l = (lane >> 4) * 8;
    const int b_row_l = (lane & 7) + ((lane >> 4) << 3);
    const int b_col_l = ((lane >> 3) & 1) * 8;

    // --- banded score GEMM: (Qh+Ql) x Kh
    float scacc[3][4];
#pragma unroll
    for (int t = 0; t < 3; t++)
#pragma unroll
        for (int i = 0; i < 4; i++) scacc[t][i] = 0.0f;

#pragma unroll
    for (int ks = 0; ks < 2; ks++) {
        const int kb = ks * 16;
        uint32_t qa[4], qb[4];
        const uint32_t aoff = (mt * 16 + a_row_l) * (KSTR * 2) + (kb + a_col_l) * 2;
        ldmx4(qa, sb + AOFF_QH + aoff);
        ldmx4(qb, sb + AOFF_QL + aoff);
        const uint32_t b0off = (mt * 16 + nhf * 16 + b_row_l) * (KSTR * 2) + (kb + b_col_l) * 2;
        const uint32_t b1off = (mt * 16 + 32 + b_row_l) * (KSTR * 2) + (kb + b_col_l) * 2;
        uint32_t k0h[4], k1h[4];
        ldmx4(k0h, sb + AOFF_KH + b0off);
        ldmx4(k1h, sb + AOFF_KH + b1off);
#pragma unroll
        for (int j = 0; j < 2; j++) {
            mma_fp16(scacc[j], qa[0], qa[1], qa[2], qa[3], k0h[2 * j], k0h[2 * j + 1]);
            mma_fp16(scacc[j], qb[0], qb[1], qb[2], qb[3], k0h[2 * j], k0h[2 * j + 1]);
        }
        mma_fp16(scacc[2], qa[0], qa[1], qa[2], qa[3], k1h[2 * nhf], k1h[2 * nhf + 1]);
        mma_fp16(scacc[2], qb[0], qb[1], qb[2], qb[3], k1h[2 * nhf], k1h[2 * nhf + 1]);
    }

    // --- mask + exp + banded P store (single fp16) + denominator partials
    const int rr0 = grp;
    const int rr1 = grp + 8;
    const int prow0 = mt * 16 + grp;
    const int prow1 = prow0 + 8;
    float sA = 0.0f, sB = 0.0f;
#pragma unroll
    for (int t = 0; t < 3; t++) {
        const int cc0 = ((t < 2) ? (nhf * 16 + t * 8) : (32 + nhf * 8)) + 2 * tig;
        const int cc1 = cc0 + 1;
        const int gbase = l0 + mt * 16;
        const float m00 = (cc0 >= rr0 && cc0 <= rr0 + 32 && gbase + cc0 >= 32) ? 0.0f : NEG;
        const float m01 = (cc1 >= rr0 && cc1 <= rr0 + 32 && gbase + cc1 >= 32) ? 0.0f : NEG;
        const float m10 = (cc0 >= rr1 && cc0 <= rr1 + 32 && gbase + cc0 >= 32) ? 0.0f : NEG;
        const float m11 = (cc1 >= rr1 && cc1 <= rr1 + 32 && gbase + cc1 >= 32) ? 0.0f : NEG;
        const float e00 = __expf(scacc[t][0] + m00);
        const float e01 = __expf(scacc[t][1] + m01);
        const float e10 = __expf(scacc[t][2] + m10);
        const float e11 = __expf(scacc[t][3] + m11);
        sA += e00 + e01;
        sB += e10 + e11;
        const int bo0 = (prow0 * PSTR + cc0) * 2;
        const int bo1 = (prow1 * PSTR + cc0) * 2;
        *reinterpret_cast<uint32_t*>(dsm + AOFF_PH + bo0) = pack1(e00, e01);
        *reinterpret_cast<uint32_t*>(dsm + AOFF_PH + bo1) = pack1(e10, e11);
    }
    sA += __shfl_xor_sync(0xFFFFFFFFu, sA, 1);
    sA += __shfl_xor_sync(0xFFFFFFFFu, sA, 2);
    sB += __shfl_xor_sync(0xFFFFFFFFu, sB, 1);
    sB += __shfl_xor_sync(0xFFFFFFFFu, sB, 2);
    if (tig == 0) {
        *reinterpret_cast<float*>(dsm + AOFF_DEN + (prow0 * 2 + nhf) * 4) = sA;
        *reinterpret_cast<float*>(dsm + AOFF_DEN + (prow1 * 2 + nhf) * 4) = sB;
    }
    __syncthreads();

    // --- banded output GEMM: P x (Vh+Vl)
    float oacc[2][4];
#pragma unroll
    for (int j = 0; j < 2; j++)
#pragma unroll
        for (int i = 0; i < 4; i++) oacc[j][i] = 0.0f;

#pragma unroll
    for (int ks = 0; ks < 3; ks++) {
        const int kb = ks * 16;
        uint32_t pa[4];
        const uint32_t aoff = (mt * 16 + a_row_l) * (PSTR * 2) + (kb + a_col_l) * 2;
        ldmx4(pa, sb + AOFF_PH + aoff);
        const uint32_t voff =
            (mt * 16 + kb + a_row_l) * (KSTR * 2) + nhf * 32 + (lane >> 4) * 16;
        uint32_t vth[4], vtl[4];
        ldmx4t(vth, sb + AOFF_VH + voff);
        ldmx4t(vtl, sb + AOFF_VL + voff);
#pragma unroll
        for (int j = 0; j < 2; j++) {
            mma_fp16(oacc[j], pa[0], pa[1], pa[2], pa[3], vth[2 * j], vth[2 * j + 1]);
            mma_fp16(oacc[j], pa[0], pa[1], pa[2], pa[3], vtl[2 * j], vtl[2 * j + 1]);
        }
    }

    // --- normalize + store fp16 hi/lo planes
    const float dA = *reinterpret_cast<float*>(dsm + AOFF_DEN + prow0 * 8) +
                     *reinterpret_cast<float*>(dsm + AOFF_DEN + prow0 * 8 + 4);
    const float dB = *reinterpret_cast<float*>(dsm + AOFF_DEN + prow1 * 8) +
                     *reinterpret_cast<float*>(dsm + AOFF_DEN + prow1 * 8 + 4);
    const float invA = 1.0f / dA;
    const float invB = 1.0f / dB;
    const size_t base0 = ((size_t)(l0 + prow0) * NB + n) * EE + h * HD;
    const size_t base1 = ((size_t)(l0 + prow1) * NB + n) * EE + h * HD;
#pragma unroll
    for (int j = 0; j < 2; j++) {
        const int d0 = nhf * 16 + j * 8 + 2 * tig;
        uint32_t hi0, lo0, hi1, lo1;
        pack2(oacc[j][0] * invA, oacc[j][1] * invA, hi0, lo0);
        pack2(oacc[j][2] * invB, oacc[j][3] * invB, hi1, lo1);
        *reinterpret_cast<uint32_t*>(oh + base0 + d0) = hi0;
        *reinterpret_cast<uint32_t*>(ol + base0 + d0) = lo0;
        *reinterpret_cast<uint32_t*>(oh + base1 + d0) = hi1;
        *reinterpret_cast<uint32_t*>(ol + base1 + d0) = lo1;
    }
}

// ---------------------------------------------------------------------------
extern "C" void kernel_launch(void* const* d_in, const int* in_sizes, int n_in,
                              void* d_out, int out_size)
{
    const float* query = (const float*)d_in[0];
    const float* key   = (const float*)d_in[1];
    const float* value = (const float*)d_in[2];
    const float* w_in  = (const float*)d_in[3];
    const float* b_in  = (const float*)d_in[4];
    const float* w_out = (const float*)d_in[5];
    const float* b_out = (const float*)d_in[6];
    float* out = (float*)d_out;

    __half *inh = nullptr, *inl = nullptr, *hi = nullptr, *lo = nullptr;
    __half *wh = nullptr;
    cudaGetSymbolAddress((void**)&inh, g_inh);
    cudaGetSymbolAddress((void**)&inl, g_inl);
    cudaGetSymbolAddress((void**)&hi,  g_hi);
    cudaGetSymbolAddress((void**)&lo,  g_lo);
    cudaGetSymbolAddress((void**)&wh,  g_wh);

    __half *wih = wh;
    __half *woh = wh + 768 * 256;
    __half *ohp = hi + 3 * (size_t)LNE, *olp = lo + 3 * (size_t)LNE;

    cudaFuncSetAttribute(gemm_fp16<0>,
        cudaFuncAttributeMaxDynamicSharedMemorySize, SMEM_GEMM);
    cudaFuncSetAttribute(gemm_fp16<1>,
        cudaFuncAttributeMaxDynamicSharedMemorySize, SMEM_GEMM);
    cudaFuncSetAttribute(attn_mma,
        cudaFuncAttributeMaxDynamicSharedMemorySize, SMEM_ATTN);

    // All conversions in one launch
    cvt_all<<<3 * QB4 + WB4, 256>>>(query, key, value, w_in, w_out,
                                    inh, inl, wh);

    // Batched q/k/v projections -> fp16 planes (q scaled, k single)
    gemm_fp16<1><<<dim3(EE / BN, M / BM, 3), 256, SMEM_GEMM>>>(
        inh, inl, wih, b_in, nullptr, hi, lo);

    // Attention: q hi/lo, k single, v hi/lo -> attn-out hi/lo
    attn_mma<<<dim3(LL / TLQ, NB * HH), 256, SMEM_ATTN>>>(
        hi, lo, hi + LNE, hi + 2 * (size_t)LNE, lo + 2 * (size_t)LNE,
        ohp, olp);

    // Out-projection -> fp32 out
    gemm_fp16<0><<<dim3(EE / BN, M / BM, 1), 256, SMEM_GEMM>>>(
        ohp, olp, woh, b_out, out, nullptr, nullptr);
}

// round 16
// speedup vs baseline: 1.4218x; 1.0573x over previous
#include <cuda_runtime.h>
#include <cuda_fp16.h>
#include <math.h>
#include <stdint.h>

// Problem constants
constexpr int LL   = 8192;
constexpr int NB   = 2;
constexpr int EE   = 256;
constexpr int HH   = 8;
constexpr int HD   = 32;
constexpr int M    = LL * NB;     // 16384
constexpr int LNE  = M * EE;
constexpr int W4A  = 768 * 256 / 4;
constexpr int W4B  = 256 * 256 / 4;
constexpr int WB4  = (W4A + W4B) / 256; // 256 blocks for weights
constexpr float NEG = -1000000000.0f;
constexpr float QSCALE = 0.17677669529663687f;  // 1/sqrt(32)

// Scratch planes (fp16): proj q,k,v + attn-out (hi), lo (k slot unused)
__device__ __align__(16) __half g_hi[4 * LNE];
__device__ __align__(16) __half g_lo[4 * LNE];
__device__ __align__(16) __half g_wh[(W4A + W4B) * 4];  // weights single fp16

// ---------------------------------------------------------------------------
__device__ __forceinline__ void mma_fp16(float* c,
    uint32_t a0, uint32_t a1, uint32_t a2, uint32_t a3,
    uint32_t b0, uint32_t b1)
{
    asm volatile(
        "mma.sync.aligned.m16n8k16.row.col.f32.f16.f16.f32 "
        "{%0,%1,%2,%3}, {%4,%5,%6,%7}, {%8,%9}, {%0,%1,%2,%3};"
        : "+f"(c[0]), "+f"(c[1]), "+f"(c[2]), "+f"(c[3])
        : "r"(a0), "r"(a1), "r"(a2), "r"(a3), "r"(b0), "r"(b1));
}
__device__ __forceinline__ void ldmx4(uint32_t* r, uint32_t addr) {
    asm volatile("ldmatrix.sync.aligned.m8n8.x4.shared.b16 {%0,%1,%2,%3}, [%4];"
        : "=r"(r[0]), "=r"(r[1]), "=r"(r[2]), "=r"(r[3]) : "r"(addr));
}
__device__ __forceinline__ void ldmx4t(uint32_t* r, uint32_t addr) {
    asm volatile("ldmatrix.sync.aligned.m8n8.x4.trans.shared.b16 {%0,%1,%2,%3}, [%4];"
        : "=r"(r[0]), "=r"(r[1]), "=r"(r[2]), "=r"(r[3]) : "r"(addr));
}
__device__ __forceinline__ uint32_t smem_u32(const void* p) {
    uint32_t a;
    asm("{ .reg .u64 t; cvta.to.shared.u64 t, %1; cvt.u32.u64 %0, t; }"
        : "=r"(a) : "l"(p));
    return a;
}
__device__ __forceinline__ void cpasync16(uint32_t s, const void* g) {
    asm volatile("cp.async.cg.shared.global [%0], [%1], 16;" :: "r"(s), "l"(g));
}
__device__ __forceinline__ void cvt_hilo(float x, __half& h, __half& l) {
    h = __float2half_rn(x);
    l = __float2half_rn(x - __half2float(h));
}
__device__ __forceinline__ void pack2(float a, float b, uint32_t& hi, uint32_t& lo) {
    __half ha, la, hb, lb;
    cvt_hilo(a, ha, la);
    cvt_hilo(b, hb, lb);
    __half2 H; H.x = ha; H.y = hb;
    __half2 L; L.x = la; L.y = lb;
    hi = *reinterpret_cast<uint32_t*>(&H);
    lo = *reinterpret_cast<uint32_t*>(&L);
}
__device__ __forceinline__ uint32_t pack1(float a, float b) {
    __half2 H; H.x = __float2half_rn(a); H.y = __float2half_rn(b);
    return *reinterpret_cast<uint32_t*>(&H);
}

// ---------------------------------------------------------------------------
// Weight conversion only (w_in | w_out -> single fp16 plane).
// ---------------------------------------------------------------------------
__global__ __launch_bounds__(256) void cvt_w(
    const float* __restrict__ w_in, const float* __restrict__ w_out,
    __half* __restrict__ wh)
{
    const int i = blockIdx.x * 256 + threadIdx.x;
    float4 val = (i < W4A) ? reinterpret_cast<const float4*>(w_in)[i]
                           : reinterpret_cast<const float4*>(w_out)[i - W4A];
    __half h[4];
    h[0] = __float2half_rn(val.x);
    h[1] = __float2half_rn(val.y);
    h[2] = __float2half_rn(val.z);
    h[3] = __float2half_rn(val.w);
    reinterpret_cast<uint2*>(wh)[i] = *reinterpret_cast<uint2*>(h);
}

// ---------------------------------------------------------------------------
// GEMM fp16 2-term: C = (Ah+Al) * W^T + bias. A split hi/lo, W single fp16.
// MODE 1 (QKV): A staged DIRECTLY from fp32 input with in-register hi/lo
//               conversion (no separate cvt kernel / intermediate planes);
//               epilogue writes fp16 hi/lo planes (k lo skipped), q scaled.
// MODE 0 (out-proj): A staged from fp16 hi/lo planes via cp.async;
//               epilogue writes fp32.
// BM=128, BN=64, BK=32, W double-buffered cp.async.
// ---------------------------------------------------------------------------
constexpr int BM = 128, BN = 64, BK = 32, LDS_ = BK + 8;  // 40
constexpr int ABUF = BM * LDS_ * 2;            // 10240
constexpr int BBUF = BN * LDS_ * 2;            // 5120
constexpr int OFF_AH = 0;                      // 2 buffers
constexpr int OFF_AL = 2 * ABUF;               // 20480
constexpr int OFF_BH = 4 * ABUF;               // 40960
constexpr int SMEM_GEMM = OFF_BH + 2 * BBUF;   // 51200

template <int MODE>
__global__ __launch_bounds__(256, 3) void gemm_fp16(
    const float* __restrict__ qf,   // MODE 1: raw fp32 inputs (z-select)
    const float* __restrict__ kf,
    const float* __restrict__ vf,
    const __half* __restrict__ Ahb, // MODE 0: fp16 hi/lo planes
    const __half* __restrict__ Alb,
    const __half* __restrict__ Wb,
    const float* __restrict__ bb,
    float* __restrict__ Cf,
    __half* __restrict__ Chp,
    __half* __restrict__ Clp)
{
    extern __shared__ char dsm[];
    const uint32_t sbase = smem_u32(dsm);

    const int z = blockIdx.z;
    const float* Af = (z == 0) ? qf : (z == 1) ? kf : vf;
    const __half* Whg = Wb + (size_t)z * EE * EE;
    const float* bias = bb + z * EE;

    const int tid  = threadIdx.x;
    const int lane = tid & 31;
    const int wid  = tid >> 5;
    const int wm   = wid & 3;
    const int wn   = wid >> 2;
    const int grp  = lane >> 2;
    const int tig  = lane & 3;
    const int m0   = blockIdx.y * BM;
    const int n0   = blockIdx.x * BN;

    float acc[2][4][4];
#pragma unroll
    for (int mt = 0; mt < 2; mt++)
#pragma unroll
        for (int nt = 0; nt < 4; nt++)
#pragma unroll
            for (int i = 0; i < 4; i++) acc[mt][nt][i] = 0.0f;

    const int a_row_l = lane & 15;
    const int a_col_l = (lane >> 4) * 8;
    const int b_row_l = (lane & 7) + ((lane >> 4) << 3);
    const int b_col_l = ((lane >> 3) & 1) * 8;

    const int sa_row = tid >> 2;
    const int sa_kc  = (tid & 3) * 8;

    auto stage = [&](int buf, int k0) {
#pragma unroll
        for (int p = 0; p < 2; p++) {
            const int row = sa_row + p * 64;
            const uint32_t s = sbase + OFF_AH + buf * ABUF + row * (LDS_ * 2) + sa_kc * 2;
            if (MODE == 1) {
                // fused fp32 -> fp16 hi/lo conversion in staging
                const float* src = Af + (size_t)(m0 + row) * EE + k0 + sa_kc;
                const float4 a0 = *reinterpret_cast<const float4*>(src);
                const float4 a1 = *reinterpret_cast<const float4*>(src + 4);
                __half h[8], l[8];
                cvt_hilo(a0.x, h[0], l[0]);
                cvt_hilo(a0.y, h[1], l[1]);
                cvt_hilo(a0.z, h[2], l[2]);
                cvt_hilo(a0.w, h[3], l[3]);
                cvt_hilo(a1.x, h[4], l[4]);
                cvt_hilo(a1.y, h[5], l[5]);
                cvt_hilo(a1.z, h[6], l[6]);
                cvt_hilo(a1.w, h[7], l[7]);
                *reinterpret_cast<uint4*>(dsm + (s - sbase)) =
                    *reinterpret_cast<uint4*>(h);
                *reinterpret_cast<uint4*>(dsm + (s - sbase) + (OFF_AL - OFF_AH)) =
                    *reinterpret_cast<uint4*>(l);
            } else {
                const size_t g = (size_t)(m0 + row) * EE + k0 + sa_kc;
                cpasync16(s, Ahb + g);
                cpasync16(s + (OFF_AL - OFF_AH), Alb + g);
            }
        }
        {
            const size_t g = (size_t)(n0 + sa_row) * EE + k0 + sa_kc;
            const uint32_t s = sbase + OFF_BH + buf * BBUF + sa_row * (LDS_ * 2) + sa_kc * 2;
            cpasync16(s, Whg + g);
        }
        asm volatile("cp.async.commit_group;");
    };

    stage(0, 0);
    constexpr int NCH = EE / BK;
#pragma unroll 1
    for (int ch = 0; ch < NCH; ch++) {
        if (ch < NCH - 1) {
            stage((ch + 1) & 1, (ch + 1) * BK);
            asm volatile("cp.async.wait_group 1;");
        } else {
            asm volatile("cp.async.wait_group 0;");
        }
        __syncthreads();

        const int buf = ch & 1;
        const uint32_t sAh = sbase + OFF_AH + buf * ABUF;
        const uint32_t sAl = sbase + OFF_AL + buf * ABUF;
        const uint32_t sBh = sbase + OFF_BH + buf * BBUF;

#pragma unroll
        for (int ks = 0; ks < 2; ks++) {
            const int kb = ks * 16;
            uint32_t ah[2][4], al[2][4];
#pragma unroll
            for (int mt = 0; mt < 2; mt++) {
                const uint32_t aoff =
                    ((wm * 32 + mt * 16 + a_row_l) * LDS_ + kb + a_col_l) * 2;
                ldmx4(ah[mt], sAh + aoff);
                ldmx4(al[mt], sAl + aoff);
            }
#pragma unroll
            for (int ntp = 0; ntp < 2; ntp++) {
                const uint32_t boff =
                    ((wn * 32 + ntp * 16 + b_row_l) * LDS_ + kb + b_col_l) * 2;
                uint32_t bh[4];
                ldmx4(bh, sBh + boff);
#pragma unroll
                for (int j = 0; j < 2; j++) {
                    const int nt = ntp * 2 + j;
                    const uint32_t b0h = bh[2 * j], b1h = bh[2 * j + 1];
#pragma unroll
                    for (int mt = 0; mt < 2; mt++) {
                        mma_fp16(acc[mt][nt], ah[mt][0], ah[mt][1], ah[mt][2], ah[mt][3], b0h, b1h);
                        mma_fp16(acc[mt][nt], al[mt][0], al[mt][1], al[mt][2], al[mt][3], b0h, b1h);
                    }
                }
            }
        }
        __syncthreads();
    }

    if (MODE == 0) {
        float* C = Cf;
#pragma unroll
        for (int mt = 0; mt < 2; mt++) {
            const int r0 = m0 + wm * 32 + mt * 16 + grp;
#pragma unroll
            for (int nt = 0; nt < 4; nt++) {
                const int c = n0 + wn * 32 + nt * 8 + 2 * tig;
                const float b0v = bias[c], b1v = bias[c + 1];
                float2 o0 = make_float2(acc[mt][nt][0] + b0v, acc[mt][nt][1] + b1v);
                float2 o1 = make_float2(acc[mt][nt][2] + b0v, acc[mt][nt][3] + b1v);
                *reinterpret_cast<float2*>(&C[(size_t)r0 * EE + c]) = o0;
                *reinterpret_cast<float2*>(&C[(size_t)(r0 + 8) * EE + c]) = o1;
            }
        }
    } else {
        const float sc = (z == 0) ? QSCALE : 1.0f;
        __half* Ch = Chp + (size_t)z * LNE;
        __half* Cl = Clp + (size_t)z * LNE;
        const bool wlo = (z != 1);   // k consumed as single fp16 (B operand)
#pragma unroll
        for (int mt = 0; mt < 2; mt++) {
            const int r0 = m0 + wm * 32 + mt * 16 + grp;
#pragma unroll
            for (int nt = 0; nt < 4; nt++) {
                const int c = n0 + wn * 32 + nt * 8 + 2 * tig;
                const float b0v = bias[c], b1v = bias[c + 1];
                uint32_t hi0, lo0, hi1, lo1;
                pack2((acc[mt][nt][0] + b0v) * sc, (acc[mt][nt][1] + b1v) * sc, hi0, lo0);
                pack2((acc[mt][nt][2] + b0v) * sc, (acc[mt][nt][3] + b1v) * sc, hi1, lo1);
                *reinterpret_cast<uint32_t*>(&Ch[(size_t)r0 * EE + c]) = hi0;
                *reinterpret_cast<uint32_t*>(&Ch[(size_t)(r0 + 8) * EE + c]) = hi1;
                if (wlo) {
                    *reinterpret_cast<uint32_t*>(&Cl[(size_t)r0 * EE + c]) = lo0;
                    *reinterpret_cast<uint32_t*>(&Cl[(size_t)(r0 + 8) * EE + c]) = lo1;
                }
            }
        }
    }
}

// ---------------------------------------------------------------------------
// Banded MMA sliding-window attention, fp16 2-term (unchanged from R15).
// ---------------------------------------------------------------------------
constexpr int TLQ = 64, KR = 96;
constexpr int KSTR = 40;
constexpr int PSTR = 56;
constexpr int AOFF_QH = 0;
constexpr int AOFF_QL = AOFF_QH + TLQ * KSTR * 2;   // 5120
constexpr int AOFF_KH = AOFF_QL + TLQ * KSTR * 2;   // 10240
constexpr int AOFF_VH = AOFF_KH + KR * KSTR * 2;    // 17920
constexpr int AOFF_VL = AOFF_VH + KR * KSTR * 2;    // 25600
constexpr int AOFF_PH = AOFF_VL + KR * KSTR * 2;    // 33280
constexpr int AOFF_DEN = AOFF_PH + TLQ * PSTR * 2;  // 40448
constexpr int SMEM_ATTN = AOFF_DEN + TLQ * 2 * 4;   // 40960

__global__ __launch_bounds__(256, 3) void attn_mma(
    const __half* __restrict__ qh, const __half* __restrict__ ql,
    const __half* __restrict__ kh,
    const __half* __restrict__ vh, const __half* __restrict__ vl,
    __half* __restrict__ oh, __half* __restrict__ ol)
{
    extern __shared__ char dsm[];
    const uint32_t sb = smem_u32(dsm);

    const int nhid = blockIdx.y;
    const int n    = nhid / HH;
    const int h    = nhid % HH;
    const int l0   = blockIdx.x * TLQ;
    const int tid  = threadIdx.x;
    const int lane = tid & 31;
    const int wid  = tid >> 5;
    const int mt   = wid & 3;
    const int nhf  = wid >> 2;
    const int grp  = lane >> 2;
    const int tig  = lane & 3;

    {
        const int row = tid >> 2, ch = tid & 3;
        const size_t src = ((size_t)(l0 + row) * NB + n) * EE + h * HD + ch * 8;
        const uint32_t dst = sb + AOFF_QH + row * (KSTR * 2) + ch * 16;
        cpasync16(dst, qh + src);
        cpasync16(dst + (AOFF_QL - AOFF_QH), ql + src);
    }
#pragma unroll
    for (int i = 0; i < 2; i++) {
        const int idx = tid + i * 256;
        if (idx < KR * 4) {
            const int row = idx >> 2, ch = idx & 3;
            const int gl = l0 - 32 + row;
            const uint32_t dk = sb + AOFF_KH + row * (KSTR * 2) + ch * 16;
            const uint32_t dv = sb + AOFF_VH + row * (KSTR * 2) + ch * 16;
            if (gl >= 0) {
                const size_t src = ((size_t)gl * NB + n) * EE + h * HD + ch * 8;
                cpasync16(dk, kh + src);
                cpasync16(dv, vh + src);
                cpasync16(dv + (AOFF_VL - AOFF_VH), vl + src);
            } else {
                const uint4 z4 = make_uint4(0, 0, 0, 0);
                const int bo = row * (KSTR * 2) + ch * 16;
                *reinterpret_cast<uint4*>(dsm + AOFF_KH + bo) = z4;
                *reinterpret_cast<uint4*>(dsm + AOFF_VH + bo) = z4;
                *reinterpret_cast<uint4*>(dsm + AOFF_VL + bo) = z4;
            }
        }
    }
    asm volatile("cp.async.commit_group;");
    asm volatile("cp.async.wait_group 0;");
    __syncthreads();

    const int a_row_l = lane & 15;
    const int a_col_l = (lane >> 4) * 8;
    const int b_row_l = (lane & 7) + ((lane >> 4) << 3);
    const int b_col_l = ((lane >> 3) & 1) * 8;

    float scacc[3][4];
#pragma unroll
    for (int t = 0; t < 3; t++)
#pragma unroll
        for (int i = 0; i < 4; i++) scacc[t][i] = 0.0f;

#pragma unroll
    for (int ks = 0; ks < 2; ks++) {
        const int kb = ks * 16;
        uint32_t qa[4], qb[4];
        const uint32_t aoff = (mt * 16 + a_row_l) * (KSTR * 2) + (kb + a_col_l) * 2;
        ldmx4(qa, sb + AOFF_QH + aoff);
        ldmx4(qb, sb + AOFF_QL + aoff);
        const uint32_t b0off = (mt * 16 + nhf * 16 + b_row_l) * (KSTR * 2) + (kb + b_col_l) * 2;
        const uint32_t b1off = (mt * 16 + 32 + b_row_l) * (KSTR * 2) + (kb + b_col_l) * 2;
        uint32_t k0h[4], k1h[4];
        ldmx4(k0h, sb + AOFF_KH + b0off);
        ldmx4(k1h, sb + AOFF_KH + b1off);
#pragma unroll
        for (int j = 0; j < 2; j++) {
            mma_fp16(scacc[j], qa[0], qa[1], qa[2], qa[3], k0h[2 * j], k0h[2 * j + 1]);
            mma_fp16(scacc[j], qb[0], qb[1], qb[2], qb[3], k0h[2 * j], k0h[2 * j + 1]);
        }
        mma_fp16(scacc[2], qa[0], qa[1], qa[2], qa[3], k1h[2 * nhf], k1h[2 * nhf + 1]);
        mma_fp16(scacc[2], qb[0], qb[1], qb[2], qb[3], k1h[2 * nhf], k1h[2 * nhf + 1]);
    }

    const int rr0 = grp;
    const int rr1 = grp + 8;
    const int prow0 = mt * 16 + grp;
    const int prow1 = prow0 + 8;
    float sA = 0.0f, sB = 0.0f;
#pragma unroll
    for (int t = 0; t < 3; t++) {
        const int cc0 = ((t < 2) ? (nhf * 16 + t * 8) : (32 + nhf * 8)) + 2 * tig;
        const int cc1 = cc0 + 1;
        const int gbase = l0 + mt * 16;
        const float m00 = (cc0 >= rr0 && cc0 <= rr0 + 32 && gbase + cc0 >= 32) ? 0.0f : NEG;
        const float m01 = (cc1 >= rr0 && cc1 <= rr0 + 32 && gbase + cc1 >= 32) ? 0.0f : NEG;
        const float m10 = (cc0 >= rr1 && cc0 <= rr1 + 32 && gbase + cc0 >= 32) ? 0.0f : NEG;
        const float m11 = (cc1 >= rr1 && cc1 <= rr1 + 32 && gbase + cc1 >= 32) ? 0.0f : NEG;
        const float e00 = __expf(scacc[t][0] + m00);
        const float e01 = __expf(scacc[t][1] + m01);
        const float e10 = __expf(scacc[t][2] + m10);
        const float e11 = __expf(scacc[t][3] + m11);
        sA += e00 + e01;
        sB += e10 + e11;
        const int bo0 = (prow0 * PSTR + cc0) * 2;
        const int bo1 = (prow1 * PSTR + cc0) * 2;
        *reinterpret_cast<uint32_t*>(dsm + AOFF_PH + bo0) = pack1(e00, e01);
        *reinterpret_cast<uint32_t*>(dsm + AOFF_PH + bo1) = pack1(e10, e11);
    }
    sA += __shfl_xor_sync(0xFFFFFFFFu, sA, 1);
    sA += __shfl_xor_sync(0xFFFFFFFFu, sA, 2);
    sB += __shfl_xor_sync(0xFFFFFFFFu, sB, 1);
    sB += __shfl_xor_sync(0xFFFFFFFFu, sB, 2);
    if (tig == 0) {
        *reinterpret_cast<float*>(dsm + AOFF_DEN + (prow0 * 2 + nhf) * 4) = sA;
        *reinterpret_cast<float*>(dsm + AOFF_DEN + (prow1 * 2 + nhf) * 4) = sB;
    }
    __syncthreads();

    float oacc[2][4];
#pragma unroll
    for (int j = 0; j < 2; j++)
#pragma unroll
        for (int i = 0; i < 4; i++) oacc[j][i] = 0.0f;

#pragma unroll
    for (int ks = 0; ks < 3; ks++) {
        const int kb = ks * 16;
        uint32_t pa[4];
        const uint32_t aoff = (mt * 16 + a_row_l) * (PSTR * 2) + (kb + a_col_l) * 2;
        ldmx4(pa, sb + AOFF_PH + aoff);
        const uint32_t voff =
            (mt * 16 + kb + a_row_l) * (KSTR * 2) + nhf * 32 + (lane >> 4) * 16;
        uint32_t vth[4], vtl[4];
        ldmx4t(vth, sb + AOFF_VH + voff);
        ldmx4t(vtl, sb + AOFF_VL + voff);
#pragma unroll
        for (int j = 0; j < 2; j++) {
            mma_fp16(oacc[j], pa[0], pa[1], pa[2], pa[3], vth[2 * j], vth[2 * j + 1]);
            mma_fp16(oacc[j], pa[0], pa[1], pa[2], pa[3], vtl[2 * j], vtl[2 * j + 1]);
        }
    }

    const float dA = *reinterpret_cast<float*>(dsm + AOFF_DEN + prow0 * 8) +
                     *reinterpret_cast<float*>(dsm + AOFF_DEN + prow0 * 8 + 4);
    const float dB = *reinterpret_cast<float*>(dsm + AOFF_DEN + prow1 * 8) +
                     *reinterpret_cast<float*>(dsm + AOFF_DEN + prow1 * 8 + 4);
    const float invA = 1.0f / dA;
    const float invB = 1.0f / dB;
    const size_t base0 = ((size_t)(l0 + prow0) * NB + n) * EE + h * HD;
    const size_t base1 = ((size_t)(l0 + prow1) * NB + n) * EE + h * HD;
#pragma unroll
    for (int j = 0; j < 2; j++) {
        const int d0 = nhf * 16 + j * 8 + 2 * tig;
        uint32_t hi0, lo0, hi1, lo1;
        pack2(oacc[j][0] * invA, oacc[j][1] * invA, hi0, lo0);
        pack2(oacc[j][2] * invB, oacc[j][3] * invB, hi1, lo1);
        *reinterpret_cast<uint32_t*>(oh + base0 + d0) = hi0;
        *reinterpret_cast<uint32_t*>(ol + base0 + d0) = lo0;
        *reinterpret_cast<uint32_t*>(oh + base1 + d0) = hi1;
        *reinterpret_cast<uint32_t*>(ol + base1 + d0) = lo1;
    }
}

// ---------------------------------------------------------------------------
extern "C" void kernel_launch(void* const* d_in, const int* in_sizes, int n_in,
                              void* d_out, int out_size)
{
    const float* query = (const float*)d_in[0];
    const float* key   = (const float*)d_in[1];
    const float* value = (const float*)d_in[2];
    const float* w_in  = (const float*)d_in[3];
    const float* b_in  = (const float*)d_in[4];
    const float* w_out = (const float*)d_in[5];
    const float* b_out = (const float*)d_in[6];
    float* out = (float*)d_out;

    __half *hi = nullptr, *lo = nullptr, *wh = nullptr;
    cudaGetSymbolAddress((void**)&hi, g_hi);
    cudaGetSymbolAddress((void**)&lo, g_lo);
    cudaGetSymbolAddress((void**)&wh, g_wh);

    __half *wih = wh;
    __half *woh = wh + 768 * 256;
    __half *ohp = hi + 3 * (size_t)LNE, *olp = lo + 3 * (size_t)LNE;

    cudaFuncSetAttribute(gemm_fp16<0>,
        cudaFuncAttributeMaxDynamicSharedMemorySize, SMEM_GEMM);
    cudaFuncSetAttribute(gemm_fp16<1>,
        cudaFuncAttributeMaxDynamicSharedMemorySize, SMEM_GEMM);
    cudaFuncSetAttribute(attn_mma,
        cudaFuncAttributeMaxDynamicSharedMemorySize, SMEM_ATTN);

    // Weight conversion only (q/k/v conversion fused into GEMM staging)
    cvt_w<<<WB4, 256>>>(w_in, w_out, wh);

    // Batched q/k/v projections, fused input conversion -> fp16 planes
    gemm_fp16<1><<<dim3(EE / BN, M / BM, 3), 256, SMEM_GEMM>>>(
        query, key, value, nullptr, nullptr, wih, b_in, nullptr, hi, lo);

    // Attention: q hi/lo, k single, v hi/lo -> attn-out hi/lo
    attn_mma<<<dim3(LL / TLQ, NB * HH), 256, SMEM_ATTN>>>(
        hi, lo, hi + LNE, hi + 2 * (size_t)LNE, lo + 2 * (size_t)LNE,
        ohp, olp);

    // Out-projection -> fp32 out
    gemm_fp16<0><<<dim3(EE / BN, M / BM, 1), 256, SMEM_GEMM>>>(
        nullptr, nullptr, nullptr, ohp, olp, woh, b_out, out, nullptr, nullptr);
}